// round 5
// baseline (speedup 1.0000x reference)
#include <cuda_runtime.h>
#include <cuda_bf16.h>
#include <math_constants.h>

#define LOOK_LONG  63
#define NFEAT      16
#define ROW_STRIDE (LOOK_LONG * NFEAT)   // 1008 floats per batch row
#define NOUT       21
#define ROWS_PER_WARP 8                  // two pipelined groups of 4
#define WARPS_PER_BLOCK 8
#define THREADS    (WARPS_PER_BLOCK * 32)
#define ROWS_PER_BLOCK (WARPS_PER_BLOCK * ROWS_PER_WARP)   // 64
#define SSTRIDE    72                    // smem floats per row (bank-conflict-free)

__device__ __forceinline__ float grp_sum(float v) {
    v += __shfl_xor_sync(0xffffffffu, v, 4);
    v += __shfl_xor_sync(0xffffffffu, v, 2);
    v += __shfl_xor_sync(0xffffffffu, v, 1);
    return v;
}
__device__ __forceinline__ float grp_max(float v) {
    v = fmaxf(v, __shfl_xor_sync(0xffffffffu, v, 4));
    v = fmaxf(v, __shfl_xor_sync(0xffffffffu, v, 2));
    v = fmaxf(v, __shfl_xor_sync(0xffffffffu, v, 1));
    return v;
}
__device__ __forceinline__ float grp_min(float v) {
    v = fminf(v, __shfl_xor_sync(0xffffffffu, v, 4));
    v = fminf(v, __shfl_xor_sync(0xffffffffu, v, 2));
    v = fminf(v, __shfl_xor_sync(0xffffffffu, v, 1));
    return v;
}

// Compute the 21 features for one group of 4 rows (full warp cooperates).
__device__ __forceinline__ void compute_group(
    const float xv[8], float vfacc, float rsi, float momc,
    float* sr, int i, int lane, int row, int B, float* __restrict__ out)
{
    // stage r into this group's smem slice (slot 63 = 0 from lane i==7)
#pragma unroll
    for (int k = 0; k < 8; ++k) sr[i + 8 * k] = xv[k];
    __syncwarp();

    // serial pass over 8 owned values
    float sum = 0.f, ssq = 0.f, sr3 = 0.f, sab = 0.f, shs = 0.f, shq = 0.f;
    float mx = -CUDART_INF_F, mn = CUDART_INF_F;
#pragma unroll
    for (int k = 0; k < 8; ++k) {
        const float xx = xv[k];
        const float x2 = xx * xx;
        sum += xx;
        ssq += x2;
        sr3 = fmaf(x2, xx, sr3);
        sab += fabsf(xx);
        if (k == 5) { const bool p = (i >= 2); shs += p ? xx : 0.f; shq += p ? x2 : 0.f; }
        if (k >= 6) { shs += xx; shq += x2; }     // t>=48 in short window (xv[7]=0 for i==7)
        if (k == 7) { const bool v7 = (i < 7);
                      mx = v7 ? fmaxf(mx, xx) : mx;
                      mn = v7 ? fminf(mn, xx) : mn; }
        else        { mx = fmaxf(mx, xx); mn = fminf(mn, xx); }
    }

    // lag-1 products
    float abacc = 0.f;
#pragma unroll
    for (int k = 0; k < 8; ++k) {
        int idx = i + 8 * k + 1;
        if (k == 7) idx = (idx > 63) ? 63 : idx;
        abacc = fmaf(xv[k], sr[idx], abacc);
    }

    // subgroup reductions (one instruction serves 4 rows)
    sum   = grp_sum(sum);
    ssq   = grp_sum(ssq);
    sr3   = grp_sum(sr3);
    sab   = grp_sum(sab);
    shs   = grp_sum(shs);
    shq   = grp_sum(shq);
    abacc = grp_sum(abacc);
    vfacc = grp_sum(vfacc);
    mx    = grp_max(mx);
    mn    = grp_min(mn);

    // sliding-window stds: windows 0..7 (lane i), window 8 (all lanes)
    float ws = 0.f, wq = 0.f;
    const int wbase = 41 - 5 * i;
#pragma unroll
    for (int k = 0; k < 22; ++k) {
        const float v = sr[wbase + k];
        ws += v;
        wq = fmaf(v, v, wq);
    }
    const float vs_i = sqrtf(fmaxf(0.f, (wq - ws * ws * (1.0f / 22.0f))) * (1.0f / 21.0f));
    float w8s = 0.f, w8q = 0.f;
#pragma unroll
    for (int k = 0; k < 22; ++k) {
        const float v = sr[1 + k];
        w8s += v;
        w8q = fmaf(v, v, w8q);
    }
    const float vs8 = sqrtf(fmaxf(0.f, (w8q - w8s * w8s * (1.0f / 22.0f))) * (1.0f / 21.0f));

    const float vs_sum  = grp_sum(vs_i) + vs8;
    const float vs_sum2 = grp_sum(vs_i * vs_i) + vs8 * vs8;
    const float m_vs = vs_sum * (1.0f / 9.0f);
    const float vol_persistence = sqrtf(fmaxf(0.f, vs_sum2 * (1.0f / 9.0f) - m_vs * m_vs));
    const float vs0 = __shfl_sync(0xffffffffu, vs_i, lane & ~7);
    const float vol_trend = vs0 - vs8;

    const float n = 63.0f;
    const float mean = sum / n;
    const float var_long = fmaxf(0.f, (ssq - sum * sum / n)) * (1.0f / 62.0f);
    const float vol_long = sqrtf(var_long);
    const float var_s = fmaxf(0.f, (shq - shs * shs * (1.0f / 21.0f))) * (1.0f / 20.0f);
    const float vol_short = sqrtf(var_s);
    const float vol_ratio = vol_short / (vol_long + 1e-8f);
    const float high_vol = (vol_short > 0.03f) ? 1.0f : 0.0f;
    const float med_vol  = ((vol_short >= 0.01f) && (vol_short <= 0.03f)) ? 1.0f : 0.0f;
    const float low_vol  = (vol_short < 0.01f) ? 1.0f : 0.0f;

    const float rfirst = sr[0], rlast = sr[62], r42 = sr[42];
    const float sa  = sum - rlast;
    const float sb  = sum - rfirst;
    const float saa = ssq - rlast * rlast;
    const float sbb = ssq - rfirst * rfirst;
    const float cnum = abacc - sa * sb * (1.0f / 62.0f);
    const float cden = sqrtf((saa - sa * sa * (1.0f / 62.0f)) * (sbb - sb * sb * (1.0f / 62.0f)));
    const float corr = cnum / cden;
    const float trend_strength = (corr != corr) ? 0.5f : fabsf(corr);

    float skewness = 0.0f;
    if (vol_long >= 1e-8f) {
        const float c3 = sr3 - 3.0f * mean * ssq + 2.0f * mean * mean * sum;
        skewness = (c3 / n) / (vol_long * vol_long * vol_long);
    }

    const float momentum_short = rlast / (r42 + 1e-8f) - 1.0f;
    const float return_range = mx - mn;
    const float vol_feature_mean = vfacc * (1.0f / 21.0f);
    const float abs_mean = sab / n;

    float a0, a1, a2 = 0.0f;
    switch (i) {
        case 0: a0 = high_vol;  a1 = skewness;        a2 = 0.0f;            break;
        case 1: a0 = med_vol;   a1 = momentum_short;  a2 = 0.02f;           break;
        case 2: a0 = low_vol;   a1 = rsi;             a2 = vol_persistence; break;
        case 3: a0 = trend_strength; a1 = vol_feature_mean; a2 = vol_trend; break;
        case 4: a0 = vol_ratio; a1 = momc;            a2 = 0.0f;            break;
        case 5: a0 = mean;      a1 = 0.0f;            break;
        case 6: a0 = abs_mean;  a1 = 1.0f;            break;
        default:a0 = return_range; a1 = 1.0f;         break;
    }
    if (row < B) {
        float* o = out + (size_t)row * NOUT;
        o[i]     = a0;
        o[i + 8] = a1;
        if (i < 5) o[i + 16] = a2;
    }
}

__global__ __launch_bounds__(THREADS)
void regime_feature_kernel(const float* __restrict__ x,
                           float* __restrict__ out,
                           int B) {
    const int lane = threadIdx.x & 31;
    const int wrp  = threadIdx.x >> 5;
    const int s    = lane >> 3;          // sub-row 0..3
    const int i    = lane & 7;           // lane within sub-row

    const int rbase = blockIdx.x * ROWS_PER_BLOCK + wrp * ROWS_PER_WARP;
    const int row0 = rbase + s;          // group 0
    const int row1 = rbase + 4 + s;      // group 1
    const int r0c = (row0 < B) ? row0 : (B - 1);
    const int r1c = (row1 < B) ? row1 : (B - 1);

    __shared__ float s_r[WARPS_PER_BLOCK][ROWS_PER_WARP * SSTRIDE];
    float* sr0 = s_r[wrp] + s * SSTRIDE;
    float* sr1 = s_r[wrp] + (4 + s) * SSTRIDE;

    const float* __restrict__ x0 = x + (size_t)r0c * ROW_STRIDE;
    const float* __restrict__ x1 = x + (size_t)r1c * ROW_STRIDE;

    // ---- front-batch ALL loads for both groups (streaming, evict-first) ----
    float xv0[8], xv1[8];
#pragma unroll
    for (int k = 0; k < 8; ++k) {
        const int t = i + 8 * k;
        if (k < 7) xv0[k] = __ldcs(x0 + t * NFEAT);
        else       xv0[k] = (i < 7) ? __ldcs(x0 + t * NFEAT) : 0.0f;
    }
    float vf0 = __ldcs(x0 + (42 + i) * NFEAT + 10) + __ldcs(x0 + (50 + i) * NFEAT + 10);
    if (i < 5) vf0 += __ldcs(x0 + (58 + i) * NFEAT + 10);
    const float rsi0 = __ldcs(x0 + 62 * NFEAT + 1);
    const float mom0 = __ldcs(x0 + 62 * NFEAT + 15);

#pragma unroll
    for (int k = 0; k < 8; ++k) {
        const int t = i + 8 * k;
        if (k < 7) xv1[k] = __ldcs(x1 + t * NFEAT);
        else       xv1[k] = (i < 7) ? __ldcs(x1 + t * NFEAT) : 0.0f;
    }
    float vf1 = __ldcs(x1 + (42 + i) * NFEAT + 10) + __ldcs(x1 + (50 + i) * NFEAT + 10);
    if (i < 5) vf1 += __ldcs(x1 + (58 + i) * NFEAT + 10);
    const float rsi1 = __ldcs(x1 + 62 * NFEAT + 1);
    const float mom1 = __ldcs(x1 + 62 * NFEAT + 15);

    // ---- compute group 0 while group 1 loads are still in flight ----
    compute_group(xv0, vf0, rsi0, mom0, sr0, i, lane, row0, B, out);
    compute_group(xv1, vf1, rsi1, mom1, sr1, i, lane, row1, B, out);
}

extern "C" void kernel_launch(void* const* d_in, const int* in_sizes, int n_in,
                              void* d_out, int out_size) {
    const float* x = (const float*)d_in[0];
    float* out = (float*)d_out;
    int B = in_sizes[0] / ROW_STRIDE;
    int blocks = (B + ROWS_PER_BLOCK - 1) / ROWS_PER_BLOCK;
    regime_feature_kernel<<<blocks, THREADS>>>(x, out, B);
}

// round 6
// speedup vs baseline: 1.0760x; 1.0760x over previous
#include <cuda_runtime.h>
#include <cuda_bf16.h>
#include <math_constants.h>

#define LOOK_LONG  63
#define NFEAT      16
#define ROW_STRIDE (LOOK_LONG * NFEAT)   // 1008 floats per batch row
#define NOUT       21
#define ROWS_PER_WARP 4
#define WARPS_PER_BLOCK 4
#define THREADS    (WARPS_PER_BLOCK * 32)
#define ROWS_PER_BLOCK (WARPS_PER_BLOCK * ROWS_PER_WARP)   // 16
#define SSTRIDE    72                    // smem floats per row (bank-conflict-free)

__device__ __forceinline__ float grp_sum(float v) {
    v += __shfl_xor_sync(0xffffffffu, v, 4);
    v += __shfl_xor_sync(0xffffffffu, v, 2);
    v += __shfl_xor_sync(0xffffffffu, v, 1);
    return v;
}
__device__ __forceinline__ float grp_max(float v) {
    v = fmaxf(v, __shfl_xor_sync(0xffffffffu, v, 4));
    v = fmaxf(v, __shfl_xor_sync(0xffffffffu, v, 2));
    v = fmaxf(v, __shfl_xor_sync(0xffffffffu, v, 1));
    return v;
}
__device__ __forceinline__ float grp_min(float v) {
    v = fminf(v, __shfl_xor_sync(0xffffffffu, v, 4));
    v = fminf(v, __shfl_xor_sync(0xffffffffu, v, 2));
    v = fminf(v, __shfl_xor_sync(0xffffffffu, v, 1));
    return v;
}

__global__ __launch_bounds__(THREADS)
void regime_feature_kernel(const float* __restrict__ x,
                           float* __restrict__ out,
                           int B) {
    const int lane = threadIdx.x & 31;
    const int wrp  = threadIdx.x >> 5;
    const int s    = lane >> 3;          // sub-row 0..3
    const int i    = lane & 7;           // lane within sub-row
    const int row  = blockIdx.x * ROWS_PER_BLOCK + wrp * ROWS_PER_WARP + s;
    const int row_c = (row < B) ? row : (B - 1);

    __shared__ float s_r[WARPS_PER_BLOCK][ROWS_PER_WARP * SSTRIDE];
    float* sr = s_r[wrp] + s * SSTRIDE;

    const float* __restrict__ xr = x + (size_t)row_c * ROW_STRIDE;

    // ---- front-batched loads: 8 r values (t = i + 8k), vf, rsi, mom ----
    float xv[8];
#pragma unroll
    for (int k = 0; k < 8; ++k) {
        const int t = i + 8 * k;
        if (k < 7) xv[k] = xr[t * NFEAT];
        else       xv[k] = (i < 7) ? xr[t * NFEAT] : 0.0f;   // t=63 -> 0
    }
    float vfacc = xr[(42 + i) * NFEAT + 10] + xr[(50 + i) * NFEAT + 10];
    if (i < 5) vfacc += xr[(58 + i) * NFEAT + 10];
    const float rsi  = xr[62 * NFEAT + 1];
    const float momc = xr[62 * NFEAT + 15];

    // ---- stage r into smem (slot 63 gets 0 from the invalid lane) ----
#pragma unroll
    for (int k = 0; k < 8; ++k) sr[i + 8 * k] = xv[k];
    __syncwarp();

    // ---- serial pass over 8 owned values ----
    float sum = 0.f, ssq = 0.f, sr3 = 0.f, sab = 0.f, shs = 0.f, shq = 0.f;
    float mx = -CUDART_INF_F, mn = CUDART_INF_F;
#pragma unroll
    for (int k = 0; k < 8; ++k) {
        const float xx = xv[k];
        const float x2 = xx * xx;
        sum += xx;
        ssq += x2;
        sr3 = fmaf(x2, xx, sr3);
        sab += fabsf(xx);
        if (k == 5) { const bool p = (i >= 2); shs += p ? xx : 0.f; shq += p ? x2 : 0.f; }
        if (k >= 6) { shs += xx; shq += x2; }               // t>=48 always in short window
        if (k == 7) { const bool v7 = (i < 7);
                      mx = v7 ? fmaxf(mx, xx) : mx;
                      mn = v7 ? fminf(mn, xx) : mn; }
        else        { mx = fmaxf(mx, xx); mn = fminf(mn, xx); }
    }

    // ---- lag-1 products: t in 0..61 contribute; t=62 hits sr[63]=0, t=63 clamped ----
    float abacc = 0.f;
#pragma unroll
    for (int k = 0; k < 8; ++k) {
        int idx = i + 8 * k + 1;
        if (k == 7) idx = (idx > 63) ? 63 : idx;            // i=7 -> sr[63]=0
        abacc = fmaf(xv[k], sr[idx], abacc);
    }

    // ---- 3-step subgroup reductions (each instruction serves 4 rows) ----
    sum   = grp_sum(sum);
    ssq   = grp_sum(ssq);
    sr3   = grp_sum(sr3);
    sab   = grp_sum(sab);
    shs   = grp_sum(shs);
    shq   = grp_sum(shq);
    abacc = grp_sum(abacc);
    vfacc = grp_sum(vfacc);
    mx    = grp_max(mx);
    mn    = grp_min(mn);

    // ---- sliding-window stds: windows 0..7 (lane i), window 8 (all lanes) ----
    float ws = 0.f, wq = 0.f;
    const int wbase = 41 - 5 * i;        // j = 62-5i, window = r[j-21 .. j]
#pragma unroll
    for (int k = 0; k < 22; ++k) {
        const float v = sr[wbase + k];
        ws += v;
        wq = fmaf(v, v, wq);
    }
    const float vs_i = sqrtf(fmaxf(0.f, (wq - ws * ws * (1.0f / 22.0f))) * (1.0f / 21.0f));
    float w8s = 0.f, w8q = 0.f;          // window 8: j=22, r[1..22]
#pragma unroll
    for (int k = 0; k < 22; ++k) {
        const float v = sr[1 + k];
        w8s += v;
        w8q = fmaf(v, v, w8q);
    }
    const float vs8 = sqrtf(fmaxf(0.f, (w8q - w8s * w8s * (1.0f / 22.0f))) * (1.0f / 21.0f));

    const float vs_sum  = grp_sum(vs_i) + vs8;
    const float vs_sum2 = grp_sum(vs_i * vs_i) + vs8 * vs8;
    const float m_vs = vs_sum * (1.0f / 9.0f);
    const float vol_persistence = sqrtf(fmaxf(0.f, vs_sum2 * (1.0f / 9.0f) - m_vs * m_vs));
    const float vs0 = __shfl_sync(0xffffffffu, vs_i, lane & ~7);
    const float vol_trend = vs0 - vs8;

    // ---- derived scalars (uniform within each 8-lane subgroup) ----
    const float n = 63.0f;
    const float mean = sum / n;
    const float var_long = fmaxf(0.f, (ssq - sum * sum / n)) * (1.0f / 62.0f);
    const float vol_long = sqrtf(var_long);
    const float var_s = fmaxf(0.f, (shq - shs * shs * (1.0f / 21.0f))) * (1.0f / 20.0f);
    const float vol_short = sqrtf(var_s);
    const float vol_ratio = vol_short / (vol_long + 1e-8f);
    const float high_vol = (vol_short > 0.03f) ? 1.0f : 0.0f;
    const float med_vol  = ((vol_short >= 0.01f) && (vol_short <= 0.03f)) ? 1.0f : 0.0f;
    const float low_vol  = (vol_short < 0.01f) ? 1.0f : 0.0f;

    const float rfirst = sr[0], rlast = sr[62], r42 = sr[42];
    const float sa  = sum - rlast;
    const float sb  = sum - rfirst;
    const float saa = ssq - rlast * rlast;
    const float sbb = ssq - rfirst * rfirst;
    const float cnum = abacc - sa * sb * (1.0f / 62.0f);
    const float cden = sqrtf((saa - sa * sa * (1.0f / 62.0f)) * (sbb - sb * sb * (1.0f / 62.0f)));
    const float corr = cnum / cden;
    const float trend_strength = (corr != corr) ? 0.5f : fabsf(corr);

    // skewness from raw moments: sum(x-mu)^3 = sr3 - 3 mu ssq + 2 mu^2 sum
    float skewness = 0.0f;
    if (vol_long >= 1e-8f) {
        const float c3 = sr3 - 3.0f * mean * ssq + 2.0f * mean * mean * sum;
        skewness = (c3 / n) / (vol_long * vol_long * vol_long);
    }

    const float momentum_short = rlast / (r42 + 1e-8f) - 1.0f;
    const float return_range = mx - mn;
    const float vol_feature_mean = vfacc * (1.0f / 21.0f);
    const float abs_mean = sab / n;

    // ---- each lane writes features i, i+8, i+16 ----
    float a0, a1, a2 = 0.0f;
    switch (i) {
        case 0: a0 = high_vol;  a1 = skewness;        a2 = 0.0f;            break; // f16 rel_strength
        case 1: a0 = med_vol;   a1 = momentum_short;  a2 = 0.02f;           break; // f17 mkt_vol
        case 2: a0 = low_vol;   a1 = rsi;             a2 = vol_persistence; break; // f18
        case 3: a0 = trend_strength; a1 = vol_feature_mean; a2 = vol_trend; break; // f19
        case 4: a0 = vol_ratio; a1 = momc;            a2 = 0.0f;            break; // f20 regime_shift
        case 5: a0 = mean;      a1 = 0.0f;            break;                        // f13 rel_return
        case 6: a0 = abs_mean;  a1 = 1.0f;            break;                        // f14 rel_vol
        default:a0 = return_range; a1 = 1.0f;         break;                        // f15 beta
    }
    if (row < B) {
        float* o = out + (size_t)row * NOUT;
        o[i]     = a0;
        o[i + 8] = a1;
        if (i < 5) o[i + 16] = a2;
    }
}

extern "C" void kernel_launch(void* const* d_in, const int* in_sizes, int n_in,
                              void* d_out, int out_size) {
    const float* x = (const float*)d_in[0];
    float* out = (float*)d_out;
    int B = in_sizes[0] / ROW_STRIDE;
    int blocks = (B + ROWS_PER_BLOCK - 1) / ROWS_PER_BLOCK;
    regime_feature_kernel<<<blocks, THREADS>>>(x, out, B);
}